// round 2
// baseline (speedup 1.0000x reference)
#include <cuda_runtime.h>
#include <cuda_bf16.h>
#include <cstdint>
#include <cstddef>

// ---------------------------------------------------------------------------
// SimpleAttention: B=4, N=4096, D=192
//   q = query @ q_w^T ; k = key @ k_w^T ; v = value @ v_w^T
//   logits = q @ k^T + bias + mask * (-1e9)
//   weights = softmax(logits)          (output #2)
//   out = (weights @ v) @ o_w^T        (output #1)
// d_out layout: [out (B*N*192) | weights (B*N*N)]
//
// Softmax trick: logits are bounded (|l| <~ 33), so exp(l) never overflows
// fp32 and masked entries (l ~ -1e9) underflow to exactly 0. We stream
// unnormalized e = exp(l) to the weights buffer, accumulate Z = sum(e) and
// O = e @ v in one pass, then rescale weights by 1/Z in a cheap second kernel.
// ---------------------------------------------------------------------------

#define BATCH 4
#define NSEQ  4096
#define DDIM  192
#define NEGV  (-1e9f)

// scratch (device globals; no allocation allowed)
__device__ float g_Q[BATCH * NSEQ * DDIM];
__device__ float g_K[BATCH * NSEQ * DDIM];
__device__ float g_V[BATCH * NSEQ * DDIM];
__device__ float g_Z[BATCH * NSEQ];

__device__ __forceinline__ void ld4(float* dst, const float* src) {
    float4 t = *reinterpret_cast<const float4*>(src);
    dst[0] = t.x; dst[1] = t.y; dst[2] = t.z; dst[3] = t.w;
}
__device__ __forceinline__ void st4(float* dst, const float* src) {
    float4 t; t.x = src[0]; t.y = src[1]; t.z = src[2]; t.w = src[3];
    *reinterpret_cast<float4*>(dst) = t;
}

// ---------------------------------------------------------------------------
// Kernel 1: projections.  Y[r,e] = sum_d X[r,d] * W[e,d]
// grid (256 row-tiles, 1, 3 matrices), block 256
// smem: Xs[64][196] + WT[192][68]
// ---------------------------------------------------------------------------
#define PJ_XS 196
#define PJ_WS 68

__global__ void proj_kernel(const float* __restrict__ q_in,
                            const float* __restrict__ k_in,
                            const float* __restrict__ v_in,
                            const float* __restrict__ q_w,
                            const float* __restrict__ k_w,
                            const float* __restrict__ v_w) {
    extern __shared__ float sm[];
    float* Xs = sm;                   // 64 * 196 = 12544
    float* WT = sm + 64 * PJ_XS;      // 192 * 68 = 13056

    const float* X; const float* W; float* Y;
    if (blockIdx.z == 0)      { X = q_in; W = q_w; Y = g_Q; }
    else if (blockIdx.z == 1) { X = k_in; W = k_w; Y = g_K; }
    else                      { X = v_in; W = v_w; Y = g_V; }

    const int row0 = blockIdx.x * 64;
    const int tid  = threadIdx.x;
    const int ty = tid >> 4;          // 0..15
    const int tx = tid & 15;          // 0..15
    const int r0 = ty * 4;
    const int c0 = tx * 4;

    // load X tile 64 x 192 (row-major, padded)
    for (int i = tid; i < 64 * 48; i += 256) {
        int r = i / 48, e4 = i % 48;
        float4 t = *reinterpret_cast<const float4*>(&X[(size_t)(row0 + r) * DDIM + e4 * 4]);
        *reinterpret_cast<float4*>(&Xs[r * PJ_XS + e4 * 4]) = t;
    }

    for (int oc = 0; oc < DDIM; oc += 64) {
        __syncthreads();   // previous chunk compute done / Xs ready
        // load W chunk transposed: WT[d][e_local]
        for (int i = tid; i < 64 * 48; i += 256) {
            int e = i / 48, d4 = i % 48;
            float4 t = *reinterpret_cast<const float4*>(&W[(size_t)(oc + e) * DDIM + d4 * 4]);
            WT[(d4 * 4 + 0) * PJ_WS + e] = t.x;
            WT[(d4 * 4 + 1) * PJ_WS + e] = t.y;
            WT[(d4 * 4 + 2) * PJ_WS + e] = t.z;
            WT[(d4 * 4 + 3) * PJ_WS + e] = t.w;
        }
        __syncthreads();

        float acc[4][4];
        #pragma unroll
        for (int r = 0; r < 4; r++)
            #pragma unroll
            for (int c = 0; c < 4; c++) acc[r][c] = 0.f;

        #pragma unroll 2
        for (int d4 = 0; d4 < 48; d4++) {
            float xa[4][4], wb[4][4];
            #pragma unroll
            for (int r = 0; r < 4; r++) ld4(xa[r], &Xs[(r0 + r) * PJ_XS + d4 * 4]);
            #pragma unroll
            for (int dd = 0; dd < 4; dd++) ld4(wb[dd], &WT[(d4 * 4 + dd) * PJ_WS + c0]);
            #pragma unroll
            for (int dd = 0; dd < 4; dd++)
                #pragma unroll
                for (int r = 0; r < 4; r++)
                    #pragma unroll
                    for (int c = 0; c < 4; c++)
                        acc[r][c] += xa[r][dd] * wb[dd][c];
        }

        #pragma unroll
        for (int r = 0; r < 4; r++)
            st4(&Y[(size_t)(row0 + r0 + r) * DDIM + oc + c0], acc[r]);
    }
}

// ---------------------------------------------------------------------------
// Kernel 2: fused attention. grid (64 q-tiles, 4 batches), block 256.
// Per CTA: 64 q rows, loop over 64 k-tiles of 64.
// smem: q_sm[64][196] | stage (kT[192][68] / v[64][196]) | Pt[64][68] | zsum[64]
// ---------------------------------------------------------------------------
#define QS  196
#define KTS 68
#define PTS 68
#define VS  196

__global__ void attn_kernel(const float* __restrict__ attn_mask,
                            const float* __restrict__ bias,
                            const float* __restrict__ o_w,
                            float* __restrict__ out,      // B*N*192
                            float* __restrict__ wout) {   // B*N*N (unnormalized exp)
    extern __shared__ float sm[];
    float* q_sm  = sm;                       // 12544
    float* stage = sm + 64 * QS;             // 13056 (kT) / 12544 (v)
    float* Pt    = stage + 192 * KTS;        // 4352
    float* zsum  = Pt + 64 * PTS;            // 64

    const int b  = blockIdx.y;
    const int q0 = blockIdx.x * 64;
    const int tid = threadIdx.x;
    const int ty = tid >> 4, tx = tid & 15;
    const int r0 = ty * 4;
    const int c0 = tx * 4;     // S-phase column base
    const int o0 = tx * 12;    // O-phase column base

    const float* Qp = g_Q + (size_t)b * NSEQ * DDIM;
    const float* Kp = g_K + (size_t)b * NSEQ * DDIM;
    const float* Vp = g_V + (size_t)b * NSEQ * DDIM;

    // load q tile
    for (int i = tid; i < 64 * 48; i += 256) {
        int r = i / 48, e4 = i % 48;
        float4 t = *reinterpret_cast<const float4*>(&Qp[(size_t)(q0 + r) * DDIM + e4 * 4]);
        *reinterpret_cast<float4*>(&q_sm[r * QS + e4 * 4]) = t;
    }
    if (tid < 64) zsum[tid] = 0.f;

    float oacc[4][12];
    #pragma unroll
    for (int r = 0; r < 4; r++)
        #pragma unroll
        for (int c = 0; c < 12; c++) oacc[r][c] = 0.f;
    float zp[4] = {0.f, 0.f, 0.f, 0.f};

    for (int kt = 0; kt < 64; kt++) {
        const int k0 = kt * 64;
        __syncthreads();   // stage free (prev PV done), q_sm ready on first iter
        // load k tile transposed: kT[e][c]
        for (int i = tid; i < 64 * 48; i += 256) {
            int c = i / 48, e4 = i % 48;
            float4 t = *reinterpret_cast<const float4*>(&Kp[(size_t)(k0 + c) * DDIM + e4 * 4]);
            stage[(e4 * 4 + 0) * KTS + c] = t.x;
            stage[(e4 * 4 + 1) * KTS + c] = t.y;
            stage[(e4 * 4 + 2) * KTS + c] = t.z;
            stage[(e4 * 4 + 3) * KTS + c] = t.w;
        }
        __syncthreads();

        // S = q @ k^T  (4x4 per thread)
        float s[4][4];
        #pragma unroll
        for (int r = 0; r < 4; r++)
            #pragma unroll
            for (int c = 0; c < 4; c++) s[r][c] = 0.f;

        #pragma unroll 2
        for (int d4 = 0; d4 < 48; d4++) {
            float qa[4][4], kb[4][4];
            #pragma unroll
            for (int r = 0; r < 4; r++) ld4(qa[r], &q_sm[(r0 + r) * QS + d4 * 4]);
            #pragma unroll
            for (int dd = 0; dd < 4; dd++) ld4(kb[dd], &stage[(d4 * 4 + dd) * KTS + c0]);
            #pragma unroll
            for (int dd = 0; dd < 4; dd++)
                #pragma unroll
                for (int r = 0; r < 4; r++)
                    #pragma unroll
                    for (int c = 0; c < 4; c++)
                        s[r][c] += qa[r][dd] * kb[dd][c];
        }

        // exp(S + bias + mask*NEG): write unnormalized weights, track rowsum
        #pragma unroll
        for (int r = 0; r < 4; r++) {
            size_t off = ((size_t)b * NSEQ + (q0 + r0 + r)) * (size_t)NSEQ + k0 + c0;
            float4 bb = *reinterpret_cast<const float4*>(&bias[off]);
            float4 mm = *reinterpret_cast<const float4*>(&attn_mask[off]);
            float p0 = __expf(s[r][0] + bb.x + mm.x * NEGV);
            float p1 = __expf(s[r][1] + bb.y + mm.y * NEGV);
            float p2 = __expf(s[r][2] + bb.z + mm.z * NEGV);
            float p3 = __expf(s[r][3] + bb.w + mm.w * NEGV);
            zp[r] += (p0 + p1) + (p2 + p3);
            float4 pv; pv.x = p0; pv.y = p1; pv.z = p2; pv.w = p3;
            *reinterpret_cast<float4*>(&wout[off]) = pv;
            s[r][0] = p0; s[r][1] = p1; s[r][2] = p2; s[r][3] = p3;
        }
        // transpose P into smem: Pt[col][row]
        #pragma unroll
        for (int c = 0; c < 4; c++) {
            float col[4] = { s[0][c], s[1][c], s[2][c], s[3][c] };
            st4(&Pt[(c0 + c) * PTS + r0], col);
        }

        __syncthreads();   // kT reads done -> reuse stage for v; Pt not yet read
        // load v tile (row-major)
        for (int i = tid; i < 64 * 48; i += 256) {
            int r = i / 48, e4 = i % 48;
            float4 t = *reinterpret_cast<const float4*>(&Vp[(size_t)(k0 + r) * DDIM + e4 * 4]);
            *reinterpret_cast<float4*>(&stage[r * VS + e4 * 4]) = t;
        }
        __syncthreads();   // v + Pt ready

        // O += P @ v   (4 rows x 12 cols per thread)
        #pragma unroll 2
        for (int k = 0; k < 64; k++) {
            float a[4], bv[12];
            ld4(a, &Pt[k * PTS + r0]);
            ld4(bv,     &stage[k * VS + o0]);
            ld4(bv + 4, &stage[k * VS + o0 + 4]);
            ld4(bv + 8, &stage[k * VS + o0 + 8]);
            #pragma unroll
            for (int r = 0; r < 4; r++)
                #pragma unroll
                for (int c = 0; c < 12; c++)
                    oacc[r][c] += a[r] * bv[c];
        }
    }

    // reduce row sums
    #pragma unroll
    for (int r = 0; r < 4; r++) atomicAdd(&zsum[r0 + r], zp[r]);
    __syncthreads();

    float invz[4];
    #pragma unroll
    for (int r = 0; r < 4; r++) invz[r] = 1.0f / zsum[r0 + r];

    // normalized O -> q_sm (reuse)
    #pragma unroll
    for (int r = 0; r < 4; r++) {
        #pragma unroll
        for (int c4 = 0; c4 < 3; c4++) {
            float t[4];
            #pragma unroll
            for (int j = 0; j < 4; j++) t[j] = oacc[r][c4 * 4 + j] * invz[r];
            st4(&q_sm[(r0 + r) * QS + o0 + c4 * 4], t);
        }
    }
    if (tid < 64) g_Z[b * NSEQ + q0 + tid] = zsum[tid];
    __syncthreads();

    // output projection: out[r,o] = sum_e O[r,e] * o_w[o,e]
    float op[4][12];
    #pragma unroll
    for (int r = 0; r < 4; r++)
        #pragma unroll
        for (int c = 0; c < 12; c++) op[r][c] = 0.f;

    #pragma unroll 2
    for (int e4 = 0; e4 < 48; e4++) {
        float oa[4][4];
        #pragma unroll
        for (int r = 0; r < 4; r++) ld4(oa[r], &q_sm[(r0 + r) * QS + e4 * 4]);
        float wv[12][4];
        #pragma unroll
        for (int c = 0; c < 12; c++) ld4(wv[c], &o_w[(size_t)(o0 + c) * DDIM + e4 * 4]);
        #pragma unroll
        for (int dd = 0; dd < 4; dd++)
            #pragma unroll
            for (int r = 0; r < 4; r++)
                #pragma unroll
                for (int c = 0; c < 12; c++)
                    op[r][c] += oa[r][dd] * wv[c][dd];
    }

    #pragma unroll
    for (int r = 0; r < 4; r++) {
        size_t off = ((size_t)b * NSEQ + (q0 + r0 + r)) * DDIM + o0;
        st4(&out[off],     &op[r][0]);
        st4(&out[off + 4], &op[r][4]);
        st4(&out[off + 8], &op[r][8]);
    }
}

// ---------------------------------------------------------------------------
// Kernel 3: normalize weights in place. grid 16384 (one per row), block 256.
// ---------------------------------------------------------------------------
__global__ void norm_kernel(float* __restrict__ wout) {
    const int row = blockIdx.x;
    const float inv = 1.0f / g_Z[row];
    float4* p = reinterpret_cast<float4*>(wout) + (size_t)row * (NSEQ / 4);
    const int t = threadIdx.x;
    #pragma unroll
    for (int j = 0; j < 4; j++) {
        float4 v = p[t + j * 256];
        v.x *= inv; v.y *= inv; v.z *= inv; v.w *= inv;
        p[t + j * 256] = v;
    }
}

// ---------------------------------------------------------------------------
extern "C" void kernel_launch(void* const* d_in, const int* in_sizes, int n_in,
                              void* d_out, int out_size) {
    const float* query = (const float*)d_in[0];
    const float* key_t = (const float*)d_in[1];
    const float* value = (const float*)d_in[2];
    const float* mask  = (const float*)d_in[3];
    const float* bias  = (const float*)d_in[4];
    const float* q_w   = (const float*)d_in[5];
    const float* k_w   = (const float*)d_in[6];
    const float* v_w   = (const float*)d_in[7];
    const float* o_w   = (const float*)d_in[8];

    float* out  = (float*)d_out;                               // B*N*192
    float* wout = (float*)d_out + (size_t)BATCH * NSEQ * DDIM; // B*N*N

    const int proj_smem = (64 * PJ_XS + 192 * PJ_WS) * 4;            // 102400
    const int attn_smem = (64 * QS + 192 * KTS + 64 * PTS + 64) * 4; // 120064

    cudaFuncSetAttribute(proj_kernel, cudaFuncAttributeMaxDynamicSharedMemorySize, proj_smem);
    cudaFuncSetAttribute(attn_kernel, cudaFuncAttributeMaxDynamicSharedMemorySize, attn_smem);

    dim3 pgrid((BATCH * NSEQ) / 64, 1, 3);
    proj_kernel<<<pgrid, 256, proj_smem>>>(query, key_t, value, q_w, k_w, v_w);

    dim3 agrid(NSEQ / 64, BATCH);
    attn_kernel<<<agrid, 256, attn_smem>>>(mask, bias, o_w, out, wout);

    norm_kernel<<<BATCH * NSEQ, 256>>>(wout);
}

// round 4
// speedup vs baseline: 2.3784x; 2.3784x over previous
#include <cuda_runtime.h>
#include <cuda_bf16.h>
#include <cstdint>
#include <cstddef>

// ---------------------------------------------------------------------------
// SimpleAttention B=4, N=4096, D=192 — tensor-core version (mma.sync bf16,
// 2-term split precision: x = hi + lo, 3 MMAs per product).
//
// d_out layout: [out (B*N*192) | weights (B*N*N)]
// Softmax without max-subtraction is exact-safe here (|logit| <~ 33).
// ---------------------------------------------------------------------------

#define BATCH 4
#define NSEQ  4096
#define DDIM  192
#define NEGV  (-1e9f)

// Q/K/V as interleaved bf16 (hi,lo) pairs: one uint32 per element.
__device__ uint32_t g_Q2[BATCH * NSEQ * DDIM];
__device__ uint32_t g_K2[BATCH * NSEQ * DDIM];
__device__ uint32_t g_V2[BATCH * NSEQ * DDIM];
__device__ float    g_Z [BATCH * NSEQ];

__device__ __forceinline__ void ld4(float* dst, const float* src) {
    float4 t = *reinterpret_cast<const float4*>(src);
    dst[0] = t.x; dst[1] = t.y; dst[2] = t.z; dst[3] = t.w;
}
__device__ __forceinline__ void st4(float* dst, const float* src) {
    float4 t; t.x = src[0]; t.y = src[1]; t.z = src[2]; t.w = src[3];
    *reinterpret_cast<float4*>(dst) = t;
}
__device__ __forceinline__ uint32_t bf16pair(float x) {
    __nv_bfloat16 h = __float2bfloat16_rn(x);
    __nv_bfloat16 l = __float2bfloat16_rn(x - __bfloat162float(h));
    return (uint32_t)__bfloat16_as_ushort(h) |
           ((uint32_t)__bfloat16_as_ushort(l) << 16);
}

__device__ __forceinline__ void ldsm4(uint32_t f[4], uint32_t addr) {
    asm volatile("ldmatrix.sync.aligned.m8n8.x4.shared.b16 {%0,%1,%2,%3}, [%4];\n"
        : "=r"(f[0]), "=r"(f[1]), "=r"(f[2]), "=r"(f[3]) : "r"(addr));
}
__device__ __forceinline__ void ldsm4t(uint32_t f[4], uint32_t addr) {
    asm volatile("ldmatrix.sync.aligned.m8n8.x4.trans.shared.b16 {%0,%1,%2,%3}, [%4];\n"
        : "=r"(f[0]), "=r"(f[1]), "=r"(f[2]), "=r"(f[3]) : "r"(addr));
}
__device__ __forceinline__ void mma_bf16(float c[4], const uint32_t a[4],
                                         uint32_t b0, uint32_t b1) {
    asm volatile(
        "mma.sync.aligned.m16n8k16.row.col.f32.bf16.bf16.f32 "
        "{%0,%1,%2,%3}, {%4,%5,%6,%7}, {%8,%9}, {%0,%1,%2,%3};\n"
        : "+f"(c[0]), "+f"(c[1]), "+f"(c[2]), "+f"(c[3])
        : "r"(a[0]), "r"(a[1]), "r"(a[2]), "r"(a[3]), "r"(b0), "r"(b1));
}

// ---------------------------------------------------------------------------
// Kernel 1: projections (fp32 SIMT), emits bf16 (hi,lo) pairs.
// ---------------------------------------------------------------------------
#define PJ_XS 196
#define PJ_WS 68

__global__ void proj_kernel(const float* __restrict__ q_in,
                            const float* __restrict__ k_in,
                            const float* __restrict__ v_in,
                            const float* __restrict__ q_w,
                            const float* __restrict__ k_w,
                            const float* __restrict__ v_w) {
    extern __shared__ float sm[];
    float* Xs = sm;
    float* WT = sm + 64 * PJ_XS;

    const float* X; const float* W; uint32_t* Y;
    if (blockIdx.z == 0)      { X = q_in; W = q_w; Y = g_Q2; }
    else if (blockIdx.z == 1) { X = k_in; W = k_w; Y = g_K2; }
    else                      { X = v_in; W = v_w; Y = g_V2; }

    const int row0 = blockIdx.x * 64;
    const int tid  = threadIdx.x;
    const int ty = tid >> 4, tx = tid & 15;
    const int r0 = ty * 4, c0 = tx * 4;

    for (int i = tid; i < 64 * 48; i += 256) {
        int r = i / 48, e4 = i % 48;
        float4 t = *reinterpret_cast<const float4*>(&X[(size_t)(row0 + r) * DDIM + e4 * 4]);
        *reinterpret_cast<float4*>(&Xs[r * PJ_XS + e4 * 4]) = t;
    }

    for (int oc = 0; oc < DDIM; oc += 64) {
        __syncthreads();
        for (int i = tid; i < 64 * 48; i += 256) {
            int e = i / 48, d4 = i % 48;
            float4 t = *reinterpret_cast<const float4*>(&W[(size_t)(oc + e) * DDIM + d4 * 4]);
            WT[(d4 * 4 + 0) * PJ_WS + e] = t.x;
            WT[(d4 * 4 + 1) * PJ_WS + e] = t.y;
            WT[(d4 * 4 + 2) * PJ_WS + e] = t.z;
            WT[(d4 * 4 + 3) * PJ_WS + e] = t.w;
        }
        __syncthreads();

        float acc[4][4];
        #pragma unroll
        for (int r = 0; r < 4; r++)
            #pragma unroll
            for (int c = 0; c < 4; c++) acc[r][c] = 0.f;

        #pragma unroll 2
        for (int d4 = 0; d4 < 48; d4++) {
            float xa[4][4], wb[4][4];
            #pragma unroll
            for (int r = 0; r < 4; r++) ld4(xa[r], &Xs[(r0 + r) * PJ_XS + d4 * 4]);
            #pragma unroll
            for (int dd = 0; dd < 4; dd++) ld4(wb[dd], &WT[(d4 * 4 + dd) * PJ_WS + c0]);
            #pragma unroll
            for (int dd = 0; dd < 4; dd++)
                #pragma unroll
                for (int r = 0; r < 4; r++)
                    #pragma unroll
                    for (int c = 0; c < 4; c++)
                        acc[r][c] += xa[r][dd] * wb[dd][c];
        }

        #pragma unroll
        for (int r = 0; r < 4; r++) {
            uint4 pk;
            pk.x = bf16pair(acc[r][0]);
            pk.y = bf16pair(acc[r][1]);
            pk.z = bf16pair(acc[r][2]);
            pk.w = bf16pair(acc[r][3]);
            *reinterpret_cast<uint4*>(&Y[(size_t)(row0 + r0 + r) * DDIM + oc + c0]) = pk;
        }
    }
}

// ---------------------------------------------------------------------------
// Kernel 2: tensor-core flash attention.
// grid (32 q-tiles, 4 batches), block 256 (8 warps = 4 rowgroups x 2 colgroups)
// CTA: 128 q rows; loop over 64 k-tiles of 64.
// ---------------------------------------------------------------------------
// SMEM byte offsets (pitches: QKV rows 400B (200 halves), P rows 144B)
#define QH_OFF 0
#define QL_OFF 51200
#define KH_OFF 102400
#define KL_OFF 128000
#define PH_OFF 153600
#define PL_OFF 172032
#define Z_OFF  190464
#define ATTN_SMEM 190976

__global__ void __launch_bounds__(256, 1)
attn_kernel(const float* __restrict__ attn_mask,
            const float* __restrict__ bias,
            const float* __restrict__ o_w,
            float* __restrict__ out,
            float* __restrict__ wout) {
    extern __shared__ char smem[];
    const uint32_t SB = (uint32_t)__cvta_generic_to_shared(smem);
    float* zs = reinterpret_cast<float*>(smem + Z_OFF);

    const int b   = blockIdx.y;
    const int q0  = blockIdx.x * 128;
    const int tid = threadIdx.x;
    const int wid = tid >> 5;
    const int lane = tid & 31;
    const int g = lane >> 2, t = lane & 3;
    const int rg = wid >> 1;              // row group 0..3
    const int cg = wid & 1;               // col group 0..1
    const int rowbase = rg * 32;
    const int colbase = cg * 32;          // S-phase cols within 64-tile
    const int oc0 = cg * 96;              // PV-phase output cols

    const uint32_t* Qp = g_Q2 + (size_t)b * NSEQ * DDIM;
    const uint32_t* Kp = g_K2 + (size_t)b * NSEQ * DDIM;
    const uint32_t* Vp = g_V2 + (size_t)b * NSEQ * DDIM;

    // ---- load Q tile (128 x 192 pairs), split into hi/lo planes ----
    for (int i = tid; i < 128 * 48; i += 256) {
        int r = i / 48, c = i % 48;       // c: 16B chunk = 4 pairs
        uint4 v = *reinterpret_cast<const uint4*>(&Qp[(size_t)(q0 + r) * DDIM + c * 4]);
        uint32_t h01 = __byte_perm(v.x, v.y, 0x5410);
        uint32_t l01 = __byte_perm(v.x, v.y, 0x7632);
        uint32_t h23 = __byte_perm(v.z, v.w, 0x5410);
        uint32_t l23 = __byte_perm(v.z, v.w, 0x7632);
        *reinterpret_cast<uint2*>(smem + QH_OFF + r * 400 + c * 8) = make_uint2(h01, h23);
        *reinterpret_cast<uint2*>(smem + QL_OFF + r * 400 + c * 8) = make_uint2(l01, l23);
    }
    if (tid < 128) zs[tid] = 0.f;

    // fragment base addresses (byte offsets into smem)
    const uint32_t aHbase = SB + QH_OFF + (uint32_t)((rowbase + (lane & 15)) * 400 + ((lane >> 4) << 4));
    const uint32_t aLbase = aHbase + (QL_OFF - QH_OFF);
    const int q2 = lane >> 3, rI = lane & 7;
    const uint32_t bHbase = SB + KH_OFF +
        (uint32_t)((colbase + ((q2 >> 1) << 3) + rI) * 400 + ((q2 & 1) << 4));
    const uint32_t bLbase = bHbase + (KL_OFF - KH_OFF);
    const uint32_t pHbase = SB + PH_OFF + (uint32_t)((rowbase + (lane & 15)) * 144 + ((lane >> 4) << 4));
    const uint32_t pLbase = pHbase + (PL_OFF - PH_OFF);
    const uint32_t vHbase = SB + KH_OFF +
        (uint32_t)((((q2 & 1) << 3) + rI) * 400 + ((oc0 + ((q2 >> 1) << 3)) << 1));
    const uint32_t vLbase = vHbase + (KL_OFF - KH_OFF);

    float o[2][12][4];
    #pragma unroll
    for (int mi = 0; mi < 2; mi++)
        #pragma unroll
        for (int ni = 0; ni < 12; ni++)
            #pragma unroll
            for (int k = 0; k < 4; k++) o[mi][ni][k] = 0.f;
    float zacc[2][2] = {{0.f, 0.f}, {0.f, 0.f}};

    for (int kt = 0; kt < 64; kt++) {
        const int k0 = kt * 64;
        __syncthreads();  // Q ready (iter 0) / V reads of prev tile done

        // ---- load K tile (64 x 192 pairs) ----
        for (int i = tid; i < 64 * 48; i += 256) {
            int r = i / 48, c = i % 48;
            uint4 v = *reinterpret_cast<const uint4*>(&Kp[(size_t)(k0 + r) * DDIM + c * 4]);
            uint32_t h01 = __byte_perm(v.x, v.y, 0x5410);
            uint32_t l01 = __byte_perm(v.x, v.y, 0x7632);
            uint32_t h23 = __byte_perm(v.z, v.w, 0x5410);
            uint32_t l23 = __byte_perm(v.z, v.w, 0x7632);
            *reinterpret_cast<uint2*>(smem + KH_OFF + r * 400 + c * 8) = make_uint2(h01, h23);
            *reinterpret_cast<uint2*>(smem + KL_OFF + r * 400 + c * 8) = make_uint2(l01, l23);
        }
        __syncthreads();

        // ---- S = Q @ K^T (3-way split) ----
        float s[2][4][4];
        #pragma unroll
        for (int mi = 0; mi < 2; mi++)
            #pragma unroll
            for (int ni = 0; ni < 4; ni++)
                #pragma unroll
                for (int k = 0; k < 4; k++) s[mi][ni][k] = 0.f;

        #pragma unroll
        for (int d0 = 0; d0 < 192; d0 += 16) {
            uint32_t ah[2][4], al[2][4], bh[2][4], bl[2][4];
            ldsm4(ah[0], aHbase + d0 * 2);
            ldsm4(ah[1], aHbase + 16 * 400 + d0 * 2);
            ldsm4(al[0], aLbase + d0 * 2);
            ldsm4(al[1], aLbase + 16 * 400 + d0 * 2);
            ldsm4(bh[0], bHbase + d0 * 2);
            ldsm4(bh[1], bHbase + 16 * 400 + d0 * 2);
            ldsm4(bl[0], bLbase + d0 * 2);
            ldsm4(bl[1], bLbase + 16 * 400 + d0 * 2);
            #pragma unroll
            for (int mi = 0; mi < 2; mi++)
                #pragma unroll
                for (int ni = 0; ni < 4; ni++) {
                    uint32_t bh0 = bh[ni >> 1][(ni & 1) * 2], bh1 = bh[ni >> 1][(ni & 1) * 2 + 1];
                    uint32_t bl0 = bl[ni >> 1][(ni & 1) * 2], bl1 = bl[ni >> 1][(ni & 1) * 2 + 1];
                    mma_bf16(s[mi][ni], ah[mi], bh0, bh1);
                    mma_bf16(s[mi][ni], ah[mi], bl0, bl1);
                    mma_bf16(s[mi][ni], al[mi], bh0, bh1);
                }
        }

        // ---- epilogue: exp(S + bias + mask*NEG), write weights, split P ----
        #pragma unroll
        for (int mi = 0; mi < 2; mi++) {
            #pragma unroll
            for (int hf = 0; hf < 2; hf++) {
                const int rr = rowbase + mi * 16 + g + hf * 8;
                const size_t roff = ((size_t)(b * NSEQ + q0 + rr)) * NSEQ;
                #pragma unroll
                for (int ni = 0; ni < 4; ni++) {
                    const int lcol = colbase + ni * 8 + 2 * t;
                    const size_t off = roff + k0 + lcol;
                    float2 bb = *reinterpret_cast<const float2*>(&bias[off]);
                    float2 mm = *reinterpret_cast<const float2*>(&attn_mask[off]);
                    float p0 = __expf(s[mi][ni][hf * 2 + 0] + bb.x + mm.x * NEGV);
                    float p1 = __expf(s[mi][ni][hf * 2 + 1] + bb.y + mm.y * NEGV);
                    zacc[mi][hf] += p0 + p1;
                    *reinterpret_cast<float2*>(&wout[off]) = make_float2(p0, p1);
                    __nv_bfloat16 h0 = __float2bfloat16_rn(p0);
                    __nv_bfloat16 h1 = __float2bfloat16_rn(p1);
                    float l0 = p0 - __bfloat162float(h0);
                    float l1 = p1 - __bfloat162float(h1);
                    uint32_t hp = (uint32_t)__bfloat16_as_ushort(h0) |
                                  ((uint32_t)__bfloat16_as_ushort(h1) << 16);
                    uint32_t lp = (uint32_t)__bfloat16_as_ushort(__float2bfloat16_rn(l0)) |
                                  ((uint32_t)__bfloat16_as_ushort(__float2bfloat16_rn(l1)) << 16);
                    *reinterpret_cast<uint32_t*>(smem + PH_OFF + rr * 144 + lcol * 2) = hp;
                    *reinterpret_cast<uint32_t*>(smem + PL_OFF + rr * 144 + lcol * 2) = lp;
                }
            }
        }
        __syncthreads();  // K reads + P writes done

        // ---- load V tile into same stage ----
        for (int i = tid; i < 64 * 48; i += 256) {
            int r = i / 48, c = i % 48;
            uint4 v = *reinterpret_cast<const uint4*>(&Vp[(size_t)(k0 + r) * DDIM + c * 4]);
            uint32_t h01 = __byte_perm(v.x, v.y, 0x5410);
            uint32_t l01 = __byte_perm(v.x, v.y, 0x7632);
            uint32_t h23 = __byte_perm(v.z, v.w, 0x5410);
            uint32_t l23 = __byte_perm(v.z, v.w, 0x7632);
            *reinterpret_cast<uint2*>(smem + KH_OFF + r * 400 + c * 8) = make_uint2(h01, h23);
            *reinterpret_cast<uint2*>(smem + KL_OFF + r * 400 + c * 8) = make_uint2(l01, l23);
        }
        __syncthreads();

        // ---- O += P @ V (3-way split) ----
        #pragma unroll
        for (int kk = 0; kk < 64; kk += 16) {
            uint32_t ap[2][4], alp[2][4], vh[6][4], vl[6][4];
            ldsm4(ap[0],  pHbase + kk * 2);
            ldsm4(ap[1],  pHbase + 16 * 144 + kk * 2);
            ldsm4(alp[0], pLbase + kk * 2);
            ldsm4(alp[1], pLbase + 16 * 144 + kk * 2);
            #pragma unroll
            for (int nb = 0; nb < 6; nb++) {
                ldsm4t(vh[nb], vHbase + kk * 400 + nb * 32);
                ldsm4t(vl[nb], vLbase + kk * 400 + nb * 32);
            }
            #pragma unroll
            for (int mi = 0; mi < 2; mi++)
                #pragma unroll
                for (int ni = 0; ni < 12; ni++) {
                    uint32_t vh0 = vh[ni >> 1][(ni & 1) * 2], vh1 = vh[ni >> 1][(ni & 1) * 2 + 1];
                    uint32_t vl0 = vl[ni >> 1][(ni & 1) * 2], vl1 = vl[ni >> 1][(ni & 1) * 2 + 1];
                    mma_bf16(o[mi][ni], ap[mi], vh0, vh1);
                    mma_bf16(o[mi][ni], ap[mi], vl0, vl1);
                    mma_bf16(o[mi][ni], alp[mi], vh0, vh1);
                }
        }
    }

    // ---- finalize Z ----
    #pragma unroll
    for (int mi = 0; mi < 2; mi++)
        #pragma unroll
        for (int hf = 0; hf < 2; hf++) {
            float v = zacc[mi][hf];
            v += __shfl_xor_sync(0xffffffffu, v, 1);
            v += __shfl_xor_sync(0xffffffffu, v, 2);
            if (t == 0) atomicAdd(&zs[rowbase + mi * 16 + g + hf * 8], v);
        }
    __syncthreads();

    if (tid < 128) g_Z[b * NSEQ + q0 + tid] = zs[tid];

    // ---- normalized O -> smem fp32 (reuse Q region, pitch 196 floats) ----
    float* OF = reinterpret_cast<float*>(smem);
    #pragma unroll
    for (int mi = 0; mi < 2; mi++)
        #pragma unroll
        for (int hf = 0; hf < 2; hf++) {
            const int rr = rowbase + mi * 16 + g + hf * 8;
            const float iz = 1.0f / zs[rr];
            #pragma unroll
            for (int ni = 0; ni < 12; ni++) {
                const int col = oc0 + ni * 8 + 2 * t;
                OF[rr * 196 + col]     = o[mi][ni][hf * 2 + 0] * iz;
                OF[rr * 196 + col + 1] = o[mi][ni][hf * 2 + 1] * iz;
            }
        }
    __syncthreads();

    // ---- output projection (SIMT): out = O_n @ o_w^T ----
    {
        const int ty = tid >> 4, tx = tid & 15;
        float op[8][12];
        #pragma unroll
        for (int r = 0; r < 8; r++)
            #pragma unroll
            for (int c = 0; c < 12; c++) op[r][c] = 0.f;

        #pragma unroll 2
        for (int e4 = 0; e4 < 48; e4++) {
            float oa[8][4];
            #pragma unroll
            for (int r = 0; r < 8; r++) ld4(oa[r], &OF[(ty * 8 + r) * 196 + e4 * 4]);
            float wv[12][4];
            #pragma unroll
            for (int c = 0; c < 12; c++) ld4(wv[c], &o_w[(size_t)(tx * 12 + c) * DDIM + e4 * 4]);
            #pragma unroll
            for (int dd = 0; dd < 4; dd++)
                #pragma unroll
                for (int r = 0; r < 8; r++)
                    #pragma unroll
                    for (int c = 0; c < 12; c++)
                        op[r][c] += oa[r][dd] * wv[c][dd];
        }

        #pragma unroll
        for (int r = 0; r < 8; r++) {
            size_t off = ((size_t)(b * NSEQ + q0 + ty * 8 + r)) * DDIM + tx * 12;
            st4(&out[off],     &op[r][0]);
            st4(&out[off + 4], &op[r][4]);
            st4(&out[off + 8], &op[r][8]);
        }
    }
}

// ---------------------------------------------------------------------------
// Kernel 3: normalize weights in place.
// ---------------------------------------------------------------------------
__global__ void norm_kernel(float* __restrict__ wout) {
    const int row = blockIdx.x;
    const float inv = 1.0f / g_Z[row];
    float4* p = reinterpret_cast<float4*>(wout) + (size_t)row * (NSEQ / 4);
    const int t = threadIdx.x;
    #pragma unroll
    for (int j = 0; j < 4; j++) {
        float4 v = p[t + j * 256];
        v.x *= inv; v.y *= inv; v.z *= inv; v.w *= inv;
        p[t + j * 256] = v;
    }
}

// ---------------------------------------------------------------------------
extern "C" void kernel_launch(void* const* d_in, const int* in_sizes, int n_in,
                              void* d_out, int out_size) {
    const float* query = (const float*)d_in[0];
    const float* key_t = (const float*)d_in[1];
    const float* value = (const float*)d_in[2];
    const float* mask  = (const float*)d_in[3];
    const float* bias  = (const float*)d_in[4];
    const float* q_w   = (const float*)d_in[5];
    const float* k_w   = (const float*)d_in[6];
    const float* v_w   = (const float*)d_in[7];
    const float* o_w   = (const float*)d_in[8];

    float* out  = (float*)d_out;
    float* wout = (float*)d_out + (size_t)BATCH * NSEQ * DDIM;

    const int proj_smem = (64 * PJ_XS + 192 * PJ_WS) * 4;  // 102400

    cudaFuncSetAttribute(proj_kernel, cudaFuncAttributeMaxDynamicSharedMemorySize, proj_smem);
    cudaFuncSetAttribute(attn_kernel, cudaFuncAttributeMaxDynamicSharedMemorySize, ATTN_SMEM);

    dim3 pgrid((BATCH * NSEQ) / 64, 1, 3);
    proj_kernel<<<pgrid, 256, proj_smem>>>(query, key_t, value, q_w, k_w, v_w);

    dim3 agrid(NSEQ / 128, BATCH);
    attn_kernel<<<agrid, 256, ATTN_SMEM>>>(mask, bias, o_w, out, wout);

    norm_kernel<<<BATCH * NSEQ, 256>>>(wout);
}

// round 7
// speedup vs baseline: 2.6625x; 1.1195x over previous
#include <cuda_runtime.h>
#include <cuda_bf16.h>
#include <cstdint>
#include <cstddef>

// ---------------------------------------------------------------------------
// SimpleAttention B=4, N=4096, D=192 — mma.sync bf16, 3-MMA split precision,
// cp.async-pipelined K/V staging from precomputed hi/lo planes.
// (tcgen05 is unavailable: harness ptxas targets sm_103, which rejects it.)
// d_out layout: [out (B*N*192) | weights (B*N*N)]
// Softmax without max-subtraction is exact-safe (|logit| <~ 33).
// ---------------------------------------------------------------------------

#define BATCH 4
#define NSEQ  4096
#define DDIM  192
#define NEGV  (-1e9f)

__device__ __align__(256) __nv_bfloat16 g_Qh[BATCH * NSEQ * DDIM];
__device__ __align__(256) __nv_bfloat16 g_Ql[BATCH * NSEQ * DDIM];
__device__ __align__(256) __nv_bfloat16 g_Kh[BATCH * NSEQ * DDIM];
__device__ __align__(256) __nv_bfloat16 g_Kl[BATCH * NSEQ * DDIM];
__device__ __align__(256) __nv_bfloat16 g_Vh[BATCH * NSEQ * DDIM];
__device__ __align__(256) __nv_bfloat16 g_Vl[BATCH * NSEQ * DDIM];
__device__ float g_Z[BATCH * NSEQ];

__device__ __forceinline__ void ld4(float* d, const float* s) {
    float4 t = *reinterpret_cast<const float4*>(s);
    d[0]=t.x; d[1]=t.y; d[2]=t.z; d[3]=t.w;
}
__device__ __forceinline__ void st4(float* d, const float* s) {
    float4 t; t.x=s[0]; t.y=s[1]; t.z=s[2]; t.w=s[3];
    *reinterpret_cast<float4*>(d) = t;
}
__device__ __forceinline__ void hl_split(float x, uint16_t& h, uint16_t& l) {
    __nv_bfloat16 hh = __float2bfloat16_rn(x);
    __nv_bfloat16 ll = __float2bfloat16_rn(x - __bfloat162float(hh));
    h = __bfloat16_as_ushort(hh); l = __bfloat16_as_ushort(ll);
}

#define CP_ASYNC16(dst, src) \
    asm volatile("cp.async.cg.shared.global [%0], [%1], 16;" :: "r"(dst), "l"(src) : "memory")
#define CP_COMMIT() asm volatile("cp.async.commit_group;" ::: "memory")
#define CP_WAIT0()  asm volatile("cp.async.wait_group 0;" ::: "memory")

__device__ __forceinline__ void ldsm4(uint32_t f[4], uint32_t addr) {
    asm volatile("ldmatrix.sync.aligned.m8n8.x4.shared.b16 {%0,%1,%2,%3}, [%4];\n"
        : "=r"(f[0]), "=r"(f[1]), "=r"(f[2]), "=r"(f[3]) : "r"(addr));
}
__device__ __forceinline__ void ldsm4t(uint32_t f[4], uint32_t addr) {
    asm volatile("ldmatrix.sync.aligned.m8n8.x4.trans.shared.b16 {%0,%1,%2,%3}, [%4];\n"
        : "=r"(f[0]), "=r"(f[1]), "=r"(f[2]), "=r"(f[3]) : "r"(addr));
}
__device__ __forceinline__ void mma_bf16(float c[4], const uint32_t a[4],
                                         uint32_t b0, uint32_t b1) {
    asm volatile(
        "mma.sync.aligned.m16n8k16.row.col.f32.bf16.bf16.f32 "
        "{%0,%1,%2,%3}, {%4,%5,%6,%7}, {%8,%9}, {%0,%1,%2,%3};\n"
        : "+f"(c[0]), "+f"(c[1]), "+f"(c[2]), "+f"(c[3])
        : "r"(a[0]), "r"(a[1]), "r"(a[2]), "r"(a[3]), "r"(b0), "r"(b1));
}

// swizzled smem addressing: r = row, c = 16B-chunk within row
// 24-chunk rows (384B pitch): slot = (c&24) | ((c^r)&7)
__device__ __forceinline__ uint32_t sw24(int r, int c) {
    return (uint32_t)(r * 384 + ((((c) & 24) | (((c) ^ (r)) & 7)) << 4));
}
// 8-chunk rows (128B pitch)
__device__ __forceinline__ uint32_t sw8(int r, int c) {
    return (uint32_t)(r * 128 + ((((c) ^ (r)) & 7) << 4));
}

// ---------------------------------------------------------------------------
// Kernel 1: projections (fp32 SIMT) -> bf16 hi/lo planes.
// ---------------------------------------------------------------------------
#define PJ_XS 196
#define PJ_WS 68

__global__ void proj_kernel(const float* __restrict__ q_in,
                            const float* __restrict__ k_in,
                            const float* __restrict__ v_in,
                            const float* __restrict__ q_w,
                            const float* __restrict__ k_w,
                            const float* __restrict__ v_w) {
    extern __shared__ float sm[];
    float* Xs = sm;
    float* WT = sm + 64 * PJ_XS;

    const float* X; const float* W; __nv_bfloat16* Yh; __nv_bfloat16* Yl;
    if (blockIdx.z == 0)      { X = q_in; W = q_w; Yh = g_Qh; Yl = g_Ql; }
    else if (blockIdx.z == 1) { X = k_in; W = k_w; Yh = g_Kh; Yl = g_Kl; }
    else                      { X = v_in; W = v_w; Yh = g_Vh; Yl = g_Vl; }

    const int row0 = blockIdx.x * 64;
    const int tid  = threadIdx.x;
    const int ty = tid >> 4, tx = tid & 15;
    const int r0 = ty * 4, c0 = tx * 4;

    for (int i = tid; i < 64 * 48; i += 256) {
        int r = i / 48, e4 = i % 48;
        float4 t = *reinterpret_cast<const float4*>(&X[(size_t)(row0 + r) * DDIM + e4 * 4]);
        *reinterpret_cast<float4*>(&Xs[r * PJ_XS + e4 * 4]) = t;
    }

    for (int oc = 0; oc < DDIM; oc += 64) {
        __syncthreads();
        for (int i = tid; i < 64 * 48; i += 256) {
            int e = i / 48, d4 = i % 48;
            float4 t = *reinterpret_cast<const float4*>(&W[(size_t)(oc + e) * DDIM + d4 * 4]);
            WT[(d4 * 4 + 0) * PJ_WS + e] = t.x;
            WT[(d4 * 4 + 1) * PJ_WS + e] = t.y;
            WT[(d4 * 4 + 2) * PJ_WS + e] = t.z;
            WT[(d4 * 4 + 3) * PJ_WS + e] = t.w;
        }
        __syncthreads();

        float acc[4][4];
        #pragma unroll
        for (int r = 0; r < 4; r++)
            #pragma unroll
            for (int c = 0; c < 4; c++) acc[r][c] = 0.f;

        #pragma unroll 2
        for (int d4 = 0; d4 < 48; d4++) {
            float xa[4][4], wb[4][4];
            #pragma unroll
            for (int r = 0; r < 4; r++) ld4(xa[r], &Xs[(r0 + r) * PJ_XS + d4 * 4]);
            #pragma unroll
            for (int dd = 0; dd < 4; dd++) ld4(wb[dd], &WT[(d4 * 4 + dd) * PJ_WS + c0]);
            #pragma unroll
            for (int dd = 0; dd < 4; dd++)
                #pragma unroll
                for (int r = 0; r < 4; r++)
                    #pragma unroll
                    for (int c = 0; c < 4; c++)
                        acc[r][c] += xa[r][dd] * wb[dd][c];
        }

        #pragma unroll
        for (int r = 0; r < 4; r++) {
            uint16_t h[4], l[4];
            #pragma unroll
            for (int c = 0; c < 4; c++) hl_split(acc[r][c], h[c], l[c]);
            size_t idx = (size_t)(row0 + r0 + r) * DDIM + oc + c0;
            *reinterpret_cast<uint2*>(&Yh[idx]) =
                make_uint2((uint32_t)h[0] | ((uint32_t)h[1] << 16),
                           (uint32_t)h[2] | ((uint32_t)h[3] << 16));
            *reinterpret_cast<uint2*>(&Yl[idx]) =
                make_uint2((uint32_t)l[0] | ((uint32_t)l[1] << 16),
                           (uint32_t)l[2] | ((uint32_t)l[3] << 16));
        }
    }
}

// ---------------------------------------------------------------------------
// Kernel 2: pipelined HMMA flash attention.
// grid (32, 4), 256 threads (8 warps = 4 rowgroups x 2 colgroups).
// smem: Qh|Ql (swizzled 384B rows) | K stage | V stage | P | z
// ---------------------------------------------------------------------------
#define QHOF 0u
#define QLOF 49152u
#define KHOF 98304u
#define KLOF 122880u
#define VHOF 147456u
#define VLOF 172032u
#define PHOF 196608u
#define PLOF 212992u
#define ZOF  229376u
#define ASMEM 229888

__global__ void __launch_bounds__(256, 1)
attn_kernel(const float* __restrict__ attn_mask,
            const float* __restrict__ bias,
            const float* __restrict__ o_w,
            float* __restrict__ out,
            float* __restrict__ wout) {
    extern __shared__ char smem[];
    const uint32_t SB = (uint32_t)__cvta_generic_to_shared(smem);
    float* zs = reinterpret_cast<float*>(smem + ZOF);

    const int b    = blockIdx.y;
    const int q0   = blockIdx.x * 128;
    const int tid  = threadIdx.x;
    const int wid  = tid >> 5;
    const int lane = tid & 31;
    const int g = lane >> 2, t = lane & 3;
    const int rg = wid >> 1, cg = wid & 1;
    const int rowbase = rg * 32;
    const int colbase = cg * 32;
    const int oc0 = cg * 96;
    const int q2 = lane >> 3, rI = lane & 7;

    const size_t bN = (size_t)b * NSEQ;
    const size_t qoff = (bN + q0) * DDIM;

    // ---- prologue: cp.async Q (both planes) + K(0) ----
    for (int i = tid; i < 6144; i += 256) {
        int plane = i >= 3072;
        int ii = plane ? i - 3072 : i;
        int r = ii / 24, c = ii % 24;
        const __nv_bfloat16* src = (plane ? g_Ql : g_Qh) + qoff + (size_t)r * DDIM + c * 8;
        CP_ASYNC16(SB + (plane ? QLOF : QHOF) + sw24(r, c), src);
    }
    for (int i = tid; i < 3072; i += 256) {
        int plane = i >= 1536;
        int ii = plane ? i - 1536 : i;
        int r = ii / 24, c = ii % 24;
        const __nv_bfloat16* src = (plane ? g_Kl : g_Kh) + (bN + r) * DDIM + c * 8;
        CP_ASYNC16(SB + (plane ? KLOF : KHOF) + sw24(r, c), src);
    }
    CP_COMMIT();
    if (tid < 128) zs[tid] = 0.f;

    // fragment rows (fixed per thread)
    const int rowA = rowbase + (lane & 15);          // Q / P fragment rows
    const int rowB = colbase + ((q2 >> 1) << 3) + rI; // K fragment rows
    const int cAadd = lane >> 4;                      // chunk offset for A frags
    const int cBadd = q2 & 1;                         // chunk offset for K frags

    float o[2][12][4];
    #pragma unroll
    for (int mi = 0; mi < 2; mi++)
        #pragma unroll
        for (int ni = 0; ni < 12; ni++)
            #pragma unroll
            for (int k = 0; k < 4; k++) o[mi][ni][k] = 0.f;
    float zacc[2][2] = {{0.f, 0.f}, {0.f, 0.f}};

    for (int kt = 0; kt < 64; kt++) {
        const int k0 = kt * 64;
        CP_WAIT0();           // K(kt) [and Q on kt=0] landed
        __syncthreads();      // all warps past PV(kt-1): V stage free

        // issue V(kt) stage (overlaps S MMAs below)
        for (int i = tid; i < 3072; i += 256) {
            int plane = i >= 1536;
            int ii = plane ? i - 1536 : i;
            int r = ii / 24, c = ii % 24;
            const __nv_bfloat16* src = (plane ? g_Vl : g_Vh) + (bN + k0 + r) * DDIM + c * 8;
            CP_ASYNC16(SB + (plane ? VLOF : VHOF) + sw24(r, c), src);
        }
        CP_COMMIT();

        // ---- S = Q @ K^T (3-way split) ----
        float s[2][4][4];
        #pragma unroll
        for (int mi = 0; mi < 2; mi++)
            #pragma unroll
            for (int ni = 0; ni < 4; ni++)
                #pragma unroll
                for (int k = 0; k < 4; k++) s[mi][ni][k] = 0.f;

        #pragma unroll
        for (int d0 = 0; d0 < 192; d0 += 16) {
            const int ca = (d0 >> 3) + cAadd;
            const int cb = (d0 >> 3) + cBadd;
            uint32_t ah[2][4], al[2][4], bh[2][4], bl[2][4];
            ldsm4(ah[0], SB + QHOF + sw24(rowA, ca));
            ldsm4(ah[1], SB + QHOF + sw24(rowA + 16, ca));
            ldsm4(al[0], SB + QLOF + sw24(rowA, ca));
            ldsm4(al[1], SB + QLOF + sw24(rowA + 16, ca));
            ldsm4(bh[0], SB + KHOF + sw24(rowB, cb));
            ldsm4(bh[1], SB + KHOF + sw24(rowB + 16, cb));
            ldsm4(bl[0], SB + KLOF + sw24(rowB, cb));
            ldsm4(bl[1], SB + KLOF + sw24(rowB + 16, cb));
            #pragma unroll
            for (int mi = 0; mi < 2; mi++)
                #pragma unroll
                for (int ni = 0; ni < 4; ni++) {
                    uint32_t b0h = bh[ni >> 1][(ni & 1) * 2], b1h = bh[ni >> 1][(ni & 1) * 2 + 1];
                    uint32_t b0l = bl[ni >> 1][(ni & 1) * 2], b1l = bl[ni >> 1][(ni & 1) * 2 + 1];
                    mma_bf16(s[mi][ni], ah[mi], b0h, b1h);
                    mma_bf16(s[mi][ni], ah[mi], b0l, b1l);
                    mma_bf16(s[mi][ni], al[mi], b0h, b1h);
                }
        }

        // ---- epilogue: exp(S + bias + mask*NEG) -> wout, P hi/lo -> smem ----
        #pragma unroll
        for (int mi = 0; mi < 2; mi++) {
            #pragma unroll
            for (int hf = 0; hf < 2; hf++) {
                const int rr = rowbase + mi * 16 + g + hf * 8;
                const size_t roff = (bN + q0 + rr) * (size_t)NSEQ + k0;
                #pragma unroll
                for (int ni = 0; ni < 4; ni++) {
                    const int lcol = colbase + ni * 8 + 2 * t;
                    const size_t off = roff + lcol;
                    float2 bb = *reinterpret_cast<const float2*>(&bias[off]);
                    float2 mm = *reinterpret_cast<const float2*>(&attn_mask[off]);
                    float p0 = __expf(s[mi][ni][hf * 2 + 0] + bb.x + mm.x * NEGV);
                    float p1 = __expf(s[mi][ni][hf * 2 + 1] + bb.y + mm.y * NEGV);
                    zacc[mi][hf] += p0 + p1;
                    *reinterpret_cast<float2*>(&wout[off]) = make_float2(p0, p1);
                    uint16_t h0, l0, h1, l1;
                    hl_split(p0, h0, l0); hl_split(p1, h1, l1);
                    uint32_t pa = sw8(rr, lcol >> 3) + 4 * t;
                    *reinterpret_cast<uint32_t*>(smem + PHOF + pa) =
                        (uint32_t)h0 | ((uint32_t)h1 << 16);
                    *reinterpret_cast<uint32_t*>(smem + PLOF + pa) =
                        (uint32_t)l0 | ((uint32_t)l1 << 16);
                }
            }
        }

        CP_WAIT0();           // V(kt) landed
        __syncthreads();      // P complete; all warps' S reads of K stage done

        // issue K(kt+1) stage (overlaps PV MMAs below)
        if (kt < 63) {
            const int kn = k0 + 64;
            for (int i = tid; i < 3072; i += 256) {
                int plane = i >= 1536;
                int ii = plane ? i - 1536 : i;
                int r = ii / 24, c = ii % 24;
                const __nv_bfloat16* src = (plane ? g_Kl : g_Kh) + (bN + kn + r) * DDIM + c * 8;
                CP_ASYNC16(SB + (plane ? KLOF : KHOF) + sw24(r, c), src);
            }
            CP_COMMIT();
        }

        // ---- O += P @ V (3-way split) ----
        #pragma unroll
        for (int kk = 0; kk < 64; kk += 16) {
            const int cP = (kk >> 3) + cAadd;
            const int rV = kk + ((q2 & 1) << 3) + rI;
            uint32_t ph[2][4], pl[2][4], vh[6][4], vl[6][4];
            ldsm4(ph[0], SB + PHOF + sw8(rowA, cP));
            ldsm4(ph[1], SB + PHOF + sw8(rowA + 16, cP));
            ldsm4(pl[0], SB + PLOF + sw8(rowA, cP));
            ldsm4(pl[1], SB + PLOF + sw8(rowA + 16, cP));
            #pragma unroll
            for (int nb = 0; nb < 6; nb++) {
                const int cV = (oc0 >> 3) + (q2 >> 1) + 2 * nb;
                ldsm4t(vh[nb], SB + VHOF + sw24(rV, cV));
                ldsm4t(vl[nb], SB + VLOF + sw24(rV, cV));
            }
            #pragma unroll
            for (int mi = 0; mi < 2; mi++)
                #pragma unroll
                for (int ni = 0; ni < 12; ni++) {
                    uint32_t v0h = vh[ni >> 1][(ni & 1) * 2], v1h = vh[ni >> 1][(ni & 1) * 2 + 1];
                    uint32_t v0l = vl[ni >> 1][(ni & 1) * 2], v1l = vl[ni >> 1][(ni & 1) * 2 + 1];
                    mma_bf16(o[mi][ni], ph[mi], v0h, v1h);
                    mma_bf16(o[mi][ni], ph[mi], v0l, v1l);
                    mma_bf16(o[mi][ni], pl[mi], v0h, v1h);
                }
        }
    }

    // ---- finalize Z ----
    #pragma unroll
    for (int mi = 0; mi < 2; mi++)
        #pragma unroll
        for (int hf = 0; hf < 2; hf++) {
            float v = zacc[mi][hf];
            v += __shfl_xor_sync(0xffffffffu, v, 1);
            v += __shfl_xor_sync(0xffffffffu, v, 2);
            if (t == 0) atomicAdd(&zs[rowbase + mi * 16 + g + hf * 8], v);
        }
    __syncthreads();
    if (tid < 128) g_Z[bN + q0 + tid] = zs[tid];

    // ---- normalized O -> smem fp32 (pitch 196 floats; overwrites Q region) ----
    float* OF = reinterpret_cast<float*>(smem);
    #pragma unroll
    for (int mi = 0; mi < 2; mi++)
        #pragma unroll
        for (int hf = 0; hf < 2; hf++) {
            const int rr = rowbase + mi * 16 + g + hf * 8;
            const float iz = 1.0f / zs[rr];
            #pragma unroll
            for (int ni = 0; ni < 12; ni++) {
                const int col = oc0 + ni * 8 + 2 * t;
                OF[rr * 196 + col]     = o[mi][ni][hf * 2 + 0] * iz;
                OF[rr * 196 + col + 1] = o[mi][ni][hf * 2 + 1] * iz;
            }
        }
    __syncthreads();

    // ---- output projection (SIMT) ----
    {
        const int ty = tid >> 4, tx = tid & 15;
        float op[8][12];
        #pragma unroll
        for (int rr = 0; rr < 8; rr++)
            #pragma unroll
            for (int c = 0; c < 12; c++) op[rr][c] = 0.f;

        #pragma unroll 2
        for (int e4 = 0; e4 < 48; e4++) {
            float oa[8][4];
            #pragma unroll
            for (int rr = 0; rr < 8; rr++) ld4(oa[rr], &OF[(ty * 8 + rr) * 196 + e4 * 4]);
            float wv[12][4];
            #pragma unroll
            for (int c = 0; c < 12; c++) ld4(wv[c], &o_w[(size_t)(tx * 12 + c) * DDIM + e4 * 4]);
            #pragma unroll
            for (int dd = 0; dd < 4; dd++)
                #pragma unroll
                for (int rr = 0; rr < 8; rr++)
                    #pragma unroll
                    for (int c = 0; c < 12; c++)
                        op[rr][c] += oa[rr][dd] * wv[c][dd];
        }

        #pragma unroll
        for (int rr = 0; rr < 8; rr++) {
            size_t off = (bN + q0 + ty * 8 + rr) * (size_t)DDIM + tx * 12;
            st4(&out[off],     &op[rr][0]);
            st4(&out[off + 4], &op[rr][4]);
            st4(&out[off + 8], &op[rr][8]);
        }
    }
}

// ---------------------------------------------------------------------------
// Kernel 3: normalize weights in place.
// ---------------------------------------------------------------------------
__global__ void norm_kernel(float* __restrict__ wout) {
    const int row = blockIdx.x;
    const float inv = 1.0f / g_Z[row];
    float4* p = reinterpret_cast<float4*>(wout) + (size_t)row * (NSEQ / 4);
    const int t = threadIdx.x;
    #pragma unroll
    for (int j = 0; j < 4; j++) {
        float4 v = p[t + j * 256];
        v.x *= inv; v.y *= inv; v.z *= inv; v.w *= inv;
        p[t + j * 256] = v;
    }
}

// ---------------------------------------------------------------------------
extern "C" void kernel_launch(void* const* d_in, const int* in_sizes, int n_in,
                              void* d_out, int out_size) {
    const float* query = (const float*)d_in[0];
    const float* key_t = (const float*)d_in[1];
    const float* value = (const float*)d_in[2];
    const float* mask  = (const float*)d_in[3];
    const float* bias  = (const float*)d_in[4];
    const float* q_w   = (const float*)d_in[5];
    const float* k_w   = (const float*)d_in[6];
    const float* v_w   = (const float*)d_in[7];
    const float* o_w   = (const float*)d_in[8];

    float* out  = (float*)d_out;
    float* wout = (float*)d_out + (size_t)BATCH * NSEQ * DDIM;

    const int proj_smem = (64 * PJ_XS + 192 * PJ_WS) * 4;  // 102400
    cudaFuncSetAttribute(proj_kernel, cudaFuncAttributeMaxDynamicSharedMemorySize, proj_smem);
    cudaFuncSetAttribute(attn_kernel, cudaFuncAttributeMaxDynamicSharedMemorySize, ASMEM);

    dim3 pgrid((BATCH * NSEQ) / 64, 1, 3);
    proj_kernel<<<pgrid, 256, proj_smem>>>(query, key_t, value, q_w, k_w, v_w);

    dim3 agrid(NSEQ / 128, BATCH);
    attn_kernel<<<agrid, 256, ASMEM>>>(mask, bias, o_w, out, wout);

    norm_kernel<<<BATCH * NSEQ, 256>>>(wout);
}

// round 9
// speedup vs baseline: 3.1978x; 1.2010x over previous
#include <cuda_runtime.h>
#include <cuda_bf16.h>
#include <cstdint>
#include <cstddef>

// ---------------------------------------------------------------------------
// SimpleAttention B=4, N=4096, D=192 — all GEMMs on mma.sync bf16 with 3-MMA
// split precision. Projections: convert->HMMA. Attention: warp-owns-16-rows
// layout so P (softmax numerators) stays in registers between S and PV.
// d_out layout: [out (B*N*192) | weights (B*N*N)]
// Softmax without max-subtraction is exact-safe (|logit| <~ 33).
// ---------------------------------------------------------------------------

#define BATCH 4
#define NSEQ  4096
#define DDIM  192
#define NEGV  (-1e9f)
#define BND   (BATCH * NSEQ * DDIM)   // 3,145,728
#define WSZ   (DDIM * DDIM)           // 36,864

// input/weight hi-lo planes (written by convert_kernel)
__device__ __align__(256) __nv_bfloat16 g_Ih[3 * BND];
__device__ __align__(256) __nv_bfloat16 g_Il[3 * BND];
__device__ __align__(256) __nv_bfloat16 g_Wh[3 * WSZ];
__device__ __align__(256) __nv_bfloat16 g_Wl[3 * WSZ];
// projected q/k/v hi-lo planes (written by proj_kernel)
__device__ __align__(256) __nv_bfloat16 g_Qh[BND];
__device__ __align__(256) __nv_bfloat16 g_Ql[BND];
__device__ __align__(256) __nv_bfloat16 g_Kh[BND];
__device__ __align__(256) __nv_bfloat16 g_Kl[BND];
__device__ __align__(256) __nv_bfloat16 g_Vh[BND];
__device__ __align__(256) __nv_bfloat16 g_Vl[BND];
__device__ float g_Z[BATCH * NSEQ];

__device__ __forceinline__ void ld4(float* d, const float* s) {
    float4 t = *reinterpret_cast<const float4*>(s);
    d[0]=t.x; d[1]=t.y; d[2]=t.z; d[3]=t.w;
}
__device__ __forceinline__ void st4(float* d, const float* s) {
    float4 t; t.x=s[0]; t.y=s[1]; t.z=s[2]; t.w=s[3];
    *reinterpret_cast<float4*>(d) = t;
}
__device__ __forceinline__ void hl_split(float x, uint16_t& h, uint16_t& l) {
    __nv_bfloat16 hh = __float2bfloat16_rn(x);
    __nv_bfloat16 ll = __float2bfloat16_rn(x - __bfloat162float(hh));
    h = __bfloat16_as_ushort(hh); l = __bfloat16_as_ushort(ll);
}

#define CP_ASYNC16(dst, src) \
    asm volatile("cp.async.cg.shared.global [%0], [%1], 16;" :: "r"(dst), "l"(src) : "memory")
#define CP_COMMIT() asm volatile("cp.async.commit_group;" ::: "memory")
#define CP_WAIT0()  asm volatile("cp.async.wait_group 0;" ::: "memory")

__device__ __forceinline__ void ldsm4(uint32_t f[4], uint32_t addr) {
    asm volatile("ldmatrix.sync.aligned.m8n8.x4.shared.b16 {%0,%1,%2,%3}, [%4];\n"
        : "=r"(f[0]), "=r"(f[1]), "=r"(f[2]), "=r"(f[3]) : "r"(addr));
}
__device__ __forceinline__ void ldsm4t(uint32_t f[4], uint32_t addr) {
    asm volatile("ldmatrix.sync.aligned.m8n8.x4.trans.shared.b16 {%0,%1,%2,%3}, [%4];\n"
        : "=r"(f[0]), "=r"(f[1]), "=r"(f[2]), "=r"(f[3]) : "r"(addr));
}
__device__ __forceinline__ void mma_bf16(float c[4], const uint32_t a[4],
                                         uint32_t b0, uint32_t b1) {
    asm volatile(
        "mma.sync.aligned.m16n8k16.row.col.f32.bf16.bf16.f32 "
        "{%0,%1,%2,%3}, {%4,%5,%6,%7}, {%8,%9}, {%0,%1,%2,%3};\n"
        : "+f"(c[0]), "+f"(c[1]), "+f"(c[2]), "+f"(c[3])
        : "r"(a[0]), "r"(a[1]), "r"(a[2]), "r"(a[3]), "r"(b0), "r"(b1));
}

// swizzled smem addressing: r = row, c = 16B chunk; 384B pitch (24 chunks)
__device__ __forceinline__ uint32_t sw24(int r, int c) {
    return (uint32_t)(r * 384 + ((((c) & 24) | (((c) ^ (r)) & 7)) << 4));
}

// ---------------------------------------------------------------------------
// Kernel 0: convert inputs + weights to bf16 hi/lo planes. 4 elems/thread.
// ---------------------------------------------------------------------------
__global__ void convert_kernel(const float* __restrict__ q,
                               const float* __restrict__ k,
                               const float* __restrict__ v,
                               const float* __restrict__ qw,
                               const float* __restrict__ kw,
                               const float* __restrict__ vw) {
    const int TOT4 = (3 * BND + 3 * WSZ) / 4;
    int i4 = blockIdx.x * blockDim.x + threadIdx.x;
    if (i4 >= TOT4) return;
    int idx = i4 * 4;
    const float* src; __nv_bfloat16* dh; __nv_bfloat16* dl;
    if (idx < 3 * BND) {
        int r = idx / BND, o = idx - r * BND;
        src = (r == 0 ? q : (r == 1 ? k : v)) + o;
        dh = g_Ih + r * BND + o; dl = g_Il + r * BND + o;
    } else {
        int wi = idx - 3 * BND;
        int r = wi / WSZ, o = wi - r * WSZ;
        src = (r == 0 ? qw : (r == 1 ? kw : vw)) + o;
        dh = g_Wh + r * WSZ + o; dl = g_Wl + r * WSZ + o;
    }
    float4 x = *reinterpret_cast<const float4*>(src);
    uint16_t h[4], l[4];
    hl_split(x.x, h[0], l[0]); hl_split(x.y, h[1], l[1]);
    hl_split(x.z, h[2], l[2]); hl_split(x.w, h[3], l[3]);
    *reinterpret_cast<uint2*>(dh) =
        make_uint2((uint32_t)h[0] | ((uint32_t)h[1] << 16),
                   (uint32_t)h[2] | ((uint32_t)h[3] << 16));
    *reinterpret_cast<uint2*>(dl) =
        make_uint2((uint32_t)l[0] | ((uint32_t)l[1] << 16),
                   (uint32_t)l[2] | ((uint32_t)l[3] << 16));
}

// ---------------------------------------------------------------------------
// Kernel 1: projections via HMMA. grid (128 row-tiles, 1, 3 mats), 256 thr.
// Per CTA: 128 rows x 192 outs, K=192, out in 2 chunks of 96.
// smem: X hi/lo (128x384B each) | W chunk hi/lo (96x384B each)
// ---------------------------------------------------------------------------
#define PXH 0u
#define PXL 49152u
#define PWH 98304u
#define PWL 135168u
#define PSMEM 172032

__global__ void __launch_bounds__(256, 1)
proj_kernel() {
    extern __shared__ char smem[];
    const uint32_t SB = (uint32_t)__cvta_generic_to_shared(smem);
    const int mat  = blockIdx.z;
    const int row0 = blockIdx.x * 128;
    const int tid  = threadIdx.x;
    const int wid  = tid >> 5, lane = tid & 31;
    const int g = lane >> 2, t = lane & 3;
    const int q2 = lane >> 3, rI = lane & 7;
    const int rb = wid * 16;

    const __nv_bfloat16* Xh = g_Ih + (size_t)mat * BND + (size_t)row0 * DDIM;
    const __nv_bfloat16* Xl = g_Il + (size_t)mat * BND + (size_t)row0 * DDIM;
    const __nv_bfloat16* Wh = g_Wh + mat * WSZ;
    const __nv_bfloat16* Wl = g_Wl + mat * WSZ;
    __nv_bfloat16* Yh = (mat == 0 ? g_Qh : (mat == 1 ? g_Kh : g_Vh));
    __nv_bfloat16* Yl = (mat == 0 ? g_Ql : (mat == 1 ? g_Kl : g_Vl));

    // stage X (both planes) + W chunk 0
    for (int i = tid; i < 6144; i += 256) {
        int plane = i >= 3072;
        int ii = plane ? i - 3072 : i;
        int r = ii / 24, c = ii % 24;
        const __nv_bfloat16* src = (plane ? Xl : Xh) + (size_t)r * DDIM + c * 8;
        CP_ASYNC16(SB + (plane ? PXL : PXH) + sw24(r, c), src);
    }
    for (int i = tid; i < 4608; i += 256) {
        int plane = i >= 2304;
        int ii = plane ? i - 2304 : i;
        int r = ii / 24, c = ii % 24;
        const __nv_bfloat16* src = (plane ? Wl : Wh) + (size_t)r * DDIM + c * 8;
        CP_ASYNC16(SB + (plane ? PWL : PWH) + sw24(r, c), src);
    }
    CP_COMMIT(); CP_WAIT0(); __syncthreads();

    const int rowA = rb + (lane & 15);
    const int cAadd = lane >> 4;
    const int rowW = ((q2 >> 1) << 3) + rI;
    const int cWadd = q2 & 1;

    for (int cc = 0; cc < 2; cc++) {
        float c[12][4];
        #pragma unroll
        for (int ni = 0; ni < 12; ni++)
            #pragma unroll
            for (int j = 0; j < 4; j++) c[ni][j] = 0.f;

        #pragma unroll
        for (int d0 = 0; d0 < 192; d0 += 16) {
            const int ca = (d0 >> 3) + cAadd;
            const int cw = (d0 >> 3) + cWadd;
            uint32_t ah[4], al[4], wh[6][4], wl[6][4];
            ldsm4(ah, SB + PXH + sw24(rowA, ca));
            ldsm4(al, SB + PXL + sw24(rowA, ca));
            #pragma unroll
            for (int nb = 0; nb < 6; nb++) {
                ldsm4(wh[nb], SB + PWH + sw24(nb * 16 + rowW, cw));
                ldsm4(wl[nb], SB + PWL + sw24(nb * 16 + rowW, cw));
            }
            #pragma unroll
            for (int ni = 0; ni < 12; ni++) {
                uint32_t b0h = wh[ni >> 1][(ni & 1) * 2], b1h = wh[ni >> 1][(ni & 1) * 2 + 1];
                uint32_t b0l = wl[ni >> 1][(ni & 1) * 2], b1l = wl[ni >> 1][(ni & 1) * 2 + 1];
                mma_bf16(c[ni], ah, b0h, b1h);
                mma_bf16(c[ni], ah, b0l, b1l);
                mma_bf16(c[ni], al, b0h, b1h);
            }
        }
        __syncthreads();   // all warps done reading W chunk
        if (cc == 0) {     // stage W chunk 1 (overlaps epilogue)
            for (int i = tid; i < 4608; i += 256) {
                int plane = i >= 2304;
                int ii = plane ? i - 2304 : i;
                int r = ii / 24, ch = ii % 24;
                const __nv_bfloat16* src = (plane ? Wl : Wh) + (size_t)(96 + r) * DDIM + ch * 8;
                CP_ASYNC16(SB + (plane ? PWL : PWH) + sw24(r, ch), src);
            }
            CP_COMMIT();
        }
        // epilogue: split results, write hi/lo planes
        #pragma unroll
        for (int ni = 0; ni < 12; ni++) {
            #pragma unroll
            for (int hf = 0; hf < 2; hf++) {
                int row = row0 + rb + g + hf * 8;
                int col = cc * 96 + ni * 8 + 2 * t;
                uint16_t h0, l0, h1, l1;
                hl_split(c[ni][hf * 2 + 0], h0, l0);
                hl_split(c[ni][hf * 2 + 1], h1, l1);
                size_t idx = (size_t)row * DDIM + col;
                *reinterpret_cast<uint32_t*>(&Yh[idx]) = (uint32_t)h0 | ((uint32_t)h1 << 16);
                *reinterpret_cast<uint32_t*>(&Yl[idx]) = (uint32_t)l0 | ((uint32_t)l1 << 16);
            }
        }
        if (cc == 0) { CP_WAIT0(); __syncthreads(); }
    }
}

// ---------------------------------------------------------------------------
// Kernel 2: HMMA flash attention, P in registers.
// grid (32, 4), 256 threads; warp w owns q-rows 16w..16w+15.
// smem: Qh|Ql (128x384B) | K stage (64x384B x2) | V stage (x2) | z
// ---------------------------------------------------------------------------
#define QHOF 0u
#define QLOF 49152u
#define KHOF 98304u
#define KLOF 122880u
#define VHOF 147456u
#define VLOF 172032u
#define ZOF  196608u
#define ASMEM 197120

__global__ void __launch_bounds__(256, 1)
attn_kernel(const float* __restrict__ attn_mask,
            const float* __restrict__ bias,
            const float* __restrict__ o_w,
            float* __restrict__ out,
            float* __restrict__ wout) {
    extern __shared__ char smem[];
    const uint32_t SB = (uint32_t)__cvta_generic_to_shared(smem);
    float* zs = reinterpret_cast<float*>(smem + ZOF);

    const int b    = blockIdx.y;
    const int q0   = blockIdx.x * 128;
    const int tid  = threadIdx.x;
    const int wid  = tid >> 5, lane = tid & 31;
    const int g = lane >> 2, t = lane & 3;
    const int q2 = lane >> 3, rI = lane & 7;
    const int rb = wid * 16;

    const size_t bN = (size_t)b * NSEQ;
    const size_t qoff = (bN + q0) * DDIM;

    // prologue: stage Q (both planes) + K(0)
    for (int i = tid; i < 6144; i += 256) {
        int plane = i >= 3072;
        int ii = plane ? i - 3072 : i;
        int r = ii / 24, c = ii % 24;
        const __nv_bfloat16* src = (plane ? g_Ql : g_Qh) + qoff + (size_t)r * DDIM + c * 8;
        CP_ASYNC16(SB + (plane ? QLOF : QHOF) + sw24(r, c), src);
    }
    for (int i = tid; i < 3072; i += 256) {
        int plane = i >= 1536;
        int ii = plane ? i - 1536 : i;
        int r = ii / 24, c = ii % 24;
        const __nv_bfloat16* src = (plane ? g_Kl : g_Kh) + (bN + r) * DDIM + c * 8;
        CP_ASYNC16(SB + (plane ? KLOF : KHOF) + sw24(r, c), src);
    }
    CP_COMMIT();

    const int rowA  = rb + (lane & 15);
    const int cAadd = lane >> 4;
    const int rowK  = ((q2 >> 1) << 3) + rI;
    const int cKadd = q2 & 1;
    const int rVadd = ((q2 & 1) << 3) + rI;
    const int cVadd = q2 >> 1;

    float o[24][4];
    #pragma unroll
    for (int ni = 0; ni < 24; ni++)
        #pragma unroll
        for (int j = 0; j < 4; j++) o[ni][j] = 0.f;
    float zacc[2] = {0.f, 0.f};

    for (int kt = 0; kt < 64; kt++) {
        const int k0 = kt * 64;
        CP_WAIT0();       // K(kt) landed (and V(kt-1) group drained)
        __syncthreads();  // all warps past PV(kt-1): V stage free

        // stage V(kt) (overlaps S MMAs)
        for (int i = tid; i < 3072; i += 256) {
            int plane = i >= 1536;
            int ii = plane ? i - 1536 : i;
            int r = ii / 24, c = ii % 24;
            const __nv_bfloat16* src = (plane ? g_Vl : g_Vh) + (bN + k0 + r) * DDIM + c * 8;
            CP_ASYNC16(SB + (plane ? VLOF : VHOF) + sw24(r, c), src);
        }
        CP_COMMIT();

        // ---- S = Q @ K^T, warp's 16 rows x all 64 cols ----
        float s[8][4];
        #pragma unroll
        for (int ni = 0; ni < 8; ni++)
            #pragma unroll
            for (int j = 0; j < 4; j++) s[ni][j] = 0.f;

        #pragma unroll
        for (int d0 = 0; d0 < 192; d0 += 16) {
            const int ca = (d0 >> 3) + cAadd;
            const int ck = (d0 >> 3) + cKadd;
            uint32_t ah[4], al[4], kh[4][4], kl[4][4];
            ldsm4(ah, SB + QHOF + sw24(rowA, ca));
            ldsm4(al, SB + QLOF + sw24(rowA, ca));
            #pragma unroll
            for (int nb = 0; nb < 4; nb++) {
                ldsm4(kh[nb], SB + KHOF + sw24(nb * 16 + rowK, ck));
                ldsm4(kl[nb], SB + KLOF + sw24(nb * 16 + rowK, ck));
            }
            #pragma unroll
            for (int ni = 0; ni < 8; ni++) {
                uint32_t b0h = kh[ni >> 1][(ni & 1) * 2], b1h = kh[ni >> 1][(ni & 1) * 2 + 1];
                uint32_t b0l = kl[ni >> 1][(ni & 1) * 2], b1l = kl[ni >> 1][(ni & 1) * 2 + 1];
                mma_bf16(s[ni], ah, b0h, b1h);
                mma_bf16(s[ni], ah, b0l, b1l);
                mma_bf16(s[ni], al, b0h, b1h);
            }
        }

        // ---- epilogue: exp -> wout + P A-fragments in registers ----
        uint32_t ph[4][4], pl[4][4];
        #pragma unroll
        for (int ni = 0; ni < 8; ni++) {
            const int kk = ni >> 1, sub = ni & 1;
            #pragma unroll
            for (int hf = 0; hf < 2; hf++) {
                const int rr = rb + g + hf * 8;
                const size_t off = (bN + q0 + rr) * (size_t)NSEQ + k0 + ni * 8 + 2 * t;
                float2 bb = *reinterpret_cast<const float2*>(&bias[off]);
                float2 mm = *reinterpret_cast<const float2*>(&attn_mask[off]);
                float p0 = __expf(s[ni][hf * 2 + 0] + bb.x + mm.x * NEGV);
                float p1 = __expf(s[ni][hf * 2 + 1] + bb.y + mm.y * NEGV);
                zacc[hf] += p0 + p1;
                *reinterpret_cast<float2*>(&wout[off]) = make_float2(p0, p1);
                uint16_t h0, l0, h1, l1;
                hl_split(p0, h0, l0); hl_split(p1, h1, l1);
                ph[kk][hf + sub * 2] = (uint32_t)h0 | ((uint32_t)h1 << 16);
                pl[kk][hf + sub * 2] = (uint32_t)l0 | ((uint32_t)l1 << 16);
            }
        }

        CP_WAIT0();       // V(kt) landed
        __syncthreads();  // all warps' S reads of K stage done

        // stage K(kt+1) (overlaps PV MMAs)
        if (kt < 63) {
            const int kn = k0 + 64;
            for (int i = tid; i < 3072; i += 256) {
                int plane = i >= 1536;
                int ii = plane ? i - 1536 : i;
                int r = ii / 24, c = ii % 24;
                const __nv_bfloat16* src = (plane ? g_Kl : g_Kh) + (bN + kn + r) * DDIM + c * 8;
                CP_ASYNC16(SB + (plane ? KLOF : KHOF) + sw24(r, c), src);
            }
            CP_COMMIT();
        }

        // ---- O += P @ V (P from registers) ----
        #pragma unroll
        for (int nb = 0; nb < 12; nb++) {
            const int cV = cVadd + 2 * nb;
            #pragma unroll
            for (int kk = 0; kk < 4; kk++) {
                const int rV = kk * 16 + rVadd;
                uint32_t vh[4], vl[4];
                ldsm4t(vh, SB + VHOF + sw24(rV, cV));
                ldsm4t(vl, SB + VLOF + sw24(rV, cV));
                #pragma unroll
                for (int sub = 0; sub < 2; sub++) {
                    const int ni = 2 * nb + sub;
                    uint32_t b0h = vh[sub * 2], b1h = vh[sub * 2 + 1];
                    uint32_t b0l = vl[sub * 2], b1l = vl[sub * 2 + 1];
                    mma_bf16(o[ni], ph[kk], b0h, b1h);
                    mma_bf16(o[ni], ph[kk], b0l, b1l);
                    mma_bf16(o[ni], pl[kk], b0h, b1h);
                }
            }
        }
    }

    // ---- finalize Z (rows unique per warp: plain stores) ----
    {
        float v0 = zacc[0], v1 = zacc[1];
        v0 += __shfl_xor_sync(0xffffffffu, v0, 1);
        v0 += __shfl_xor_sync(0xffffffffu, v0, 2);
        v1 += __shfl_xor_sync(0xffffffffu, v1, 1);
        v1 += __shfl_xor_sync(0xffffffffu, v1, 2);
        if (t == 0) { zs[rb + g] = v0; zs[rb + g + 8] = v1; }
    }
    __syncthreads();
    if (tid < 128) g_Z[bN + q0 + tid] = zs[tid];

    // ---- normalized O -> smem fp32 (pitch 196; overwrites Q region) ----
    float* OF = reinterpret_cast<float*>(smem);
    #pragma unroll
    for (int hf = 0; hf < 2; hf++) {
        const int rr = rb + g + hf * 8;
        const float iz = 1.0f / zs[rr];
        #pragma unroll
        for (int ni = 0; ni < 24; ni++) {
            const int col = ni * 8 + 2 * t;
            OF[rr * 196 + col]     = o[ni][hf * 2 + 0] * iz;
            OF[rr * 196 + col + 1] = o[ni][hf * 2 + 1] * iz;
        }
    }
    __syncthreads();

    // ---- output projection (SIMT) ----
    {
        const int ty = tid >> 4, tx = tid & 15;
        float op[8][12];
        #pragma unroll
        for (int rr = 0; rr < 8; rr++)
            #pragma unroll
            for (int c = 0; c < 12; c++) op[rr][c] = 0.f;

        #pragma unroll 2
        for (int e4 = 0; e4 < 48; e4++) {
            float oa[8][4];
            #pragma unroll
            for (int rr = 0; rr < 8; rr++) ld4(oa[rr], &OF[(ty * 8 + rr) * 196 + e4 * 4]);
            float wv[12][4];
            #pragma unroll
            for (int c = 0; c < 12; c++) ld4(wv[c], &o_w[(size_t)(tx * 12 + c) * DDIM + e4 * 4]);
            #pragma unroll
            for (int dd = 0; dd < 4; dd++)
                #pragma unroll
                for (int rr = 0; rr < 8; rr++)
                    #pragma unroll
                    for (int c = 0; c < 12; c++)
                        op[rr][c] += oa[rr][dd] * wv[c][dd];
        }

        #pragma unroll
        for (int rr = 0; rr < 8; rr++) {
            size_t off = (bN + q0 + ty * 8 + rr) * (size_t)DDIM + tx * 12;
            st4(&out[off],     &op[rr][0]);
            st4(&out[off + 4], &op[rr][4]);
            st4(&out[off + 8], &op[rr][8]);
        }
    }
}

// ---------------------------------------------------------------------------
// Kernel 3: normalize weights in place.
// ---------------------------------------------------------------------------
__global__ void norm_kernel(float* __restrict__ wout) {
    const int row = blockIdx.x;
    const float inv = 1.0f / g_Z[row];
    float4* p = reinterpret_cast<float4*>(wout) + (size_t)row * (NSEQ / 4);
    const int t = threadIdx.x;
    #pragma unroll
    for (int j = 0; j < 4; j++) {
        float4 v = p[t + j * 256];
        v.x *= inv; v.y *= inv; v.z *= inv; v.w *= inv;
        p[t + j * 256] = v;
    }
}

// ---------------------------------------------------------------------------
extern "C" void kernel_launch(void* const* d_in, const int* in_sizes, int n_in,
                              void* d_out, int out_size) {
    const float* query = (const float*)d_in[0];
    const float* key_t = (const float*)d_in[1];
    const float* value = (const float*)d_in[2];
    const float* mask  = (const float*)d_in[3];
    const float* bias  = (const float*)d_in[4];
    const float* q_w   = (const float*)d_in[5];
    const float* k_w   = (const float*)d_in[6];
    const float* v_w   = (const float*)d_in[7];
    const float* o_w   = (const float*)d_in[8];

    float* out  = (float*)d_out;
    float* wout = (float*)d_out + (size_t)BATCH * NSEQ * DDIM;

    cudaFuncSetAttribute(proj_kernel, cudaFuncAttributeMaxDynamicSharedMemorySize, PSMEM);
    cudaFuncSetAttribute(attn_kernel, cudaFuncAttributeMaxDynamicSharedMemorySize, ASMEM);

    const int TOT4 = (3 * BND + 3 * WSZ) / 4;
    convert_kernel<<<(TOT4 + 255) / 256, 256>>>(query, key_t, value, q_w, k_w, v_w);

    dim3 pgrid((BATCH * NSEQ) / 128, 1, 3);
    proj_kernel<<<pgrid, 256, PSMEM>>>();

    dim3 agrid(NSEQ / 128, BATCH);
    attn_kernel<<<agrid, 256, ASMEM>>>(mask, bias, o_w, out, wout);

    norm_kernel<<<BATCH * NSEQ, 256>>>(wout);
}